// round 1
// baseline (speedup 1.0000x reference)
#include <cuda_runtime.h>
#include <math.h>

#define G      1024
#define GI     (G - 2)          // 1022 interior
#define B      4
#define NITER  21               // maxiter(=20) + 1
#define N_TOT  (B * G * G)

// iteration-invariant precomputed fields (padded G x G layout, stride G)
__device__ float g_w  [N_TOT];
__device__ float g_ch [N_TOT];   // ch[i,j] = 0.5*(w[i,j] + w[i,j+1])   (horizontal edge j -> j+1)
__device__ float g_cv [N_TOT];   // cv[i,j] = 0.5*(w[i,j] + w[i+1,j])   (vertical edge i -> i+1)
__device__ float g_F  [N_TOT];   // f*H^2 / y3
__device__ float g_iy3[N_TOT];   // 1 / y3
// ping-pong solution buffers, zero boundary
__device__ float g_u0 [N_TOT];
__device__ float g_u1 [N_TOT];

// --- kernel 1: w = exp(mu * prev_pre) over the full padded grid ---
__global__ void k_w(const float* __restrict__ prev, const float* __restrict__ mu) {
    int idx = blockIdx.x * blockDim.x + threadIdx.x;
    if (idx >= N_TOT) return;
    float m = mu[0];
    g_w[idx] = expf(m * prev[idx]);
}

// --- kernel 2: init u0 (interior = pre, border = 0) and zero u1 ---
__global__ void k_init(const float* __restrict__ pre) {
    int j = blockIdx.x * blockDim.x + threadIdx.x;
    int i = blockIdx.y;
    int b = blockIdx.z;
    if (j >= G) return;
    int idx = (b * G + i) * G + j;
    float v = 0.0f;
    if (i >= 1 && i <= G - 2 && j >= 1 && j <= G - 2)
        v = pre[(b * GI + (i - 1)) * GI + (j - 1)];
    g_u0[idx] = v;
    g_u1[idx] = 0.0f;
}

// --- kernel 3: edge coefficients + F + iy3 ---
__global__ void k_coef(const float* __restrict__ f) {
    int j = blockIdx.x * blockDim.x + threadIdx.x;
    int i = blockIdx.y;
    int b = blockIdx.z;
    if (j >= G) return;
    int idx = (b * G + i) * G + j;
    float wc = g_w[idx];

    if (j < G - 1) g_ch[idx] = 0.5f * (wc + g_w[idx + 1]);
    if (i < G - 1) g_cv[idx] = 0.5f * (wc + g_w[idx + G]);

    if (i >= 1 && i <= G - 2 && j >= 1 && j <= G - 2) {
        float wN = g_w[idx - G], wS = g_w[idx + G];
        float wW = g_w[idx - 1], wE = g_w[idx + 1];
        float y3  = 0.5f * (wN + wS + wW + wE) + 2.0f * wc;
        float iy3 = 1.0f / y3;
        const float HH = (1.0f / 1023.0f) * (1.0f / 1023.0f);
        g_iy3[idx] = iy3;
        g_F[idx]   = f[idx] * HH * iy3;
    }
}

// --- kernel 4: one Jacobi sweep.  parity selects src buffer; FINAL writes d_out layout ---
template <bool FINAL>
__global__ void k_step(int parity, float* __restrict__ out) {
    int j = blockIdx.x * blockDim.x + threadIdx.x + 1;
    int i = blockIdx.y + 1;
    int b = blockIdx.z;
    if (j > G - 2) return;
    int idx = (b * G + i) * G + j;

    const float* __restrict__ u = parity ? g_u1 : g_u0;
    float uW = u[idx - 1];
    float uE = u[idx + 1];
    float uN = u[idx - G];
    float uS = u[idx + G];

    float s = g_ch[idx - 1] * uW + g_ch[idx] * uE
            + g_cv[idx - G] * uN + g_cv[idx] * uS;
    float r = fmaf(g_iy3[idx], s, g_F[idx]);

    if (FINAL) {
        out[(b * GI + (i - 1)) * GI + (j - 1)] = r;
    } else {
        float* __restrict__ dst = parity ? g_u0 : g_u1;
        dst[idx] = r;
    }
}

extern "C" void kernel_launch(void* const* d_in, const int* in_sizes, int n_in,
                              void* d_out, int out_size) {
    const float* pre  = (const float*)d_in[0];   // [B,1,1022,1022]
    const float* f    = (const float*)d_in[1];   // [B,1,1024,1024]
    const float* mu   = (const float*)d_in[2];   // [1]
    const float* prev = (const float*)d_in[3];   // [B,1,1024,1024]
    // d_in[4] = maxiter (fixed = 20 -> 21 sweeps, static for graph capture)
    float* out = (float*)d_out;

    // precompute
    k_w<<<(N_TOT + 255) / 256, 256>>>(prev, mu);

    dim3 blk(256, 1, 1);
    dim3 grd_full((G + 255) / 256, G, B);
    k_init<<<grd_full, blk>>>(pre);
    k_coef<<<grd_full, blk>>>(f);

    // 21 Jacobi sweeps, ping-pong; last one writes d_out (unpadded layout)
    dim3 grd_in((GI + 255) / 256, GI, B);
    for (int t = 0; t < NITER - 1; ++t) {
        k_step<false><<<grd_in, blk>>>(t & 1, nullptr);
    }
    k_step<true><<<grd_in, blk>>>((NITER - 1) & 1, out);
}

// round 2
// speedup vs baseline: 1.6144x; 1.6144x over previous
#include <cuda_runtime.h>
#include <math.h>

#define G      1024
#define GI     (G - 2)          // 1022 interior
#define B      4
#define NITER  21               // maxiter(=20) + 1
#define N_TOT  (B * G * G)

// iteration-invariant fields (padded G x G layout, stride G)
__device__ float g_w  [N_TOT];   // exp(mu * prev_pre)
__device__ float g_h  [N_TOT];   // 0.5 / y3
__device__ float g_F  [N_TOT];   // f * H^2 / y3
// ping-pong solution buffers, zero boundary
__device__ float g_u0 [N_TOT];
__device__ float g_u1 [N_TOT];

// --- kernel 1: w = exp(mu * prev_pre) over the full padded grid ---
__global__ void k_w(const float* __restrict__ prev, const float* __restrict__ mu) {
    int idx = blockIdx.x * blockDim.x + threadIdx.x;
    if (idx >= N_TOT) return;
    float m = mu[0];
    g_w[idx] = expf(m * prev[idx]);
}

// --- kernel 2: init u0 (interior = pre, border = 0) and zero u1 ---
__global__ void k_init(const float* __restrict__ pre) {
    int j = blockIdx.x * blockDim.x + threadIdx.x;
    int i = blockIdx.y;
    int b = blockIdx.z;
    if (j >= G) return;
    int idx = (b * G + i) * G + j;
    float v = 0.0f;
    if (i >= 1 && i <= G - 2 && j >= 1 && j <= G - 2)
        v = pre[(b * GI + (i - 1)) * GI + (j - 1)];
    g_u0[idx] = v;
    g_u1[idx] = 0.0f;
}

// --- kernel 3: h = 0.5/y3, F = f*H^2/y3 ---
__global__ void k_coef(const float* __restrict__ f) {
    int j = blockIdx.x * blockDim.x + threadIdx.x;
    int i = blockIdx.y;
    int b = blockIdx.z;
    if (j >= G) return;
    int idx = (b * G + i) * G + j;
    if (i < 1 || i > G - 2 || j < 1 || j > G - 2) {
        g_h[idx] = 0.0f;
        g_F[idx] = 0.0f;
        return;
    }
    float wc = g_w[idx];
    float wN = g_w[idx - G], wS = g_w[idx + G];
    float wW = g_w[idx - 1], wE = g_w[idx + 1];
    float y3  = 0.5f * (wN + wS + wW + wE) + 2.0f * wc;
    float iy3 = 1.0f / y3;
    const float HH = (1.0f / 1023.0f) * (1.0f / 1023.0f);
    g_h[idx] = 0.5f * iy3;
    g_F[idx] = f[idx] * HH * iy3;
}

// --- kernel 4: one Jacobi sweep, 4 cols/thread, float4 path ---
// blockDim = (32, 8): tile of 128 cols x 8 rows.
template <bool FINAL>
__global__ void k_step(int parity, float* __restrict__ out) {
    int j0 = (blockIdx.x * blockDim.x + threadIdx.x) * 4;      // 0..1020, step 4, aligned
    int i  = blockIdx.y * blockDim.y + threadIdx.y + 1;        // 1..1022
    int b  = blockIdx.z;
    if (i > G - 2) return;
    int idx = (b * G + i) * G + j0;

    const float* __restrict__ u = parity ? g_u1 : g_u0;

    // center rows (aligned float4), plus scalar left/right neighbors
    float4 uC4 = *(const float4*)(u + idx);
    float4 uN4 = *(const float4*)(u + idx - G);
    float4 uS4 = *(const float4*)(u + idx + G);
    float  uLl = u[idx - 1];           // safe: idx >= G
    float  uRr = u[idx + 4];           // safe: i <= G-2 keeps it in-bounds

    float4 wC4 = *(const float4*)(g_w + idx);
    float4 wN4 = *(const float4*)(g_w + idx - G);
    float4 wS4 = *(const float4*)(g_w + idx + G);
    float  wLl = g_w[idx - 1];
    float  wRr = g_w[idx + 4];

    float4 h4 = *(const float4*)(g_h + idx);
    float4 F4 = *(const float4*)(g_F + idx);

    float uc[6] = { uLl, uC4.x, uC4.y, uC4.z, uC4.w, uRr };
    float wc[6] = { wLl, wC4.x, wC4.y, wC4.z, wC4.w, wRr };
    float un[4] = { uN4.x, uN4.y, uN4.z, uN4.w };
    float us[4] = { uS4.x, uS4.y, uS4.z, uS4.w };
    float wn[4] = { wN4.x, wN4.y, wN4.z, wN4.w };
    float ws[4] = { wS4.x, wS4.y, wS4.z, wS4.w };
    float hh[4] = { h4.x, h4.y, h4.z, h4.w };
    float ff[4] = { F4.x, F4.y, F4.z, F4.w };

    float r[4];
#pragma unroll
    for (int k = 0; k < 4; ++k) {
        float uW = uc[k], uE = uc[k + 2];
        float sum4 = uW + uE + un[k] + us[k];
        float s = wc[k + 1] * sum4;
        s = fmaf(wc[k],     uW,    s);
        s = fmaf(wc[k + 2], uE,    s);
        s = fmaf(wn[k],     un[k], s);
        s = fmaf(ws[k],     us[k], s);
        r[k] = fmaf(hh[k], s, ff[k]);
    }

    if (FINAL) {
        // unpadded [B, GI, GI] output, scalar stores with interior mask
        long obase = ((long)b * GI + (i - 1)) * GI;
#pragma unroll
        for (int k = 0; k < 4; ++k) {
            int j = j0 + k;
            if (j >= 1 && j <= G - 2)
                out[obase + (j - 1)] = r[k];
        }
    } else {
        float* __restrict__ dst = parity ? g_u0 : g_u1;
        if (j0 == 0) {
            dst[idx + 1] = r[1]; dst[idx + 2] = r[2]; dst[idx + 3] = r[3];
        } else if (j0 == G - 4) {
            dst[idx] = r[0]; dst[idx + 1] = r[1]; dst[idx + 2] = r[2];
        } else {
            *(float4*)(dst + idx) = make_float4(r[0], r[1], r[2], r[3]);
        }
    }
}

extern "C" void kernel_launch(void* const* d_in, const int* in_sizes, int n_in,
                              void* d_out, int out_size) {
    const float* pre  = (const float*)d_in[0];   // [B,1,1022,1022]
    const float* f    = (const float*)d_in[1];   // [B,1,1024,1024]
    const float* mu   = (const float*)d_in[2];   // [1]
    const float* prev = (const float*)d_in[3];   // [B,1,1024,1024]
    // d_in[4] = maxiter (fixed = 20 -> 21 sweeps, static for graph capture)
    float* out = (float*)d_out;

    // precompute (once per launch)
    k_w<<<(N_TOT + 255) / 256, 256>>>(prev, mu);

    dim3 blk(256, 1, 1);
    dim3 grd_full((G + 255) / 256, G, B);
    k_init<<<grd_full, blk>>>(pre);
    k_coef<<<grd_full, blk>>>(f);

    // 21 Jacobi sweeps, ping-pong; last one writes d_out (unpadded layout)
    dim3 sblk(32, 8, 1);
    dim3 sgrd(G / (32 * 4), (GI + 7) / 8, B);   // (8, 128, 4)
    for (int t = 0; t < NITER - 1; ++t) {
        k_step<false><<<sgrd, sblk>>>(t & 1, nullptr);
    }
    k_step<true><<<sgrd, sblk>>>((NITER - 1) & 1, out);
}